// round 2
// baseline (speedup 1.0000x reference)
#include <cuda_runtime.h>

#define NN 100000
#define FF 64
#define HH 8
#define DD 8
#define EE 1200000
#define HID 32

// scratch (allocation-free rule: __device__ globals)
__device__ float g_src_buf[NN * FF];
__device__ float g_dst_buf[NN * FF];
__device__ int g_idx_is64;

__device__ __forceinline__ float leaky(float x) { return fmaxf(x, 0.2f * x); }
__device__ __forceinline__ float sigm(float x) { return 1.0f / (1.0f + __expf(-x)); }

__device__ __forceinline__ void red4(float* p, float x, float y, float z, float w) {
    asm volatile("red.global.add.v4.f32 [%0], {%1,%2,%3,%4};"
                 :: "l"(p), "f"(x), "f"(y), "f"(z), "f"(w) : "memory");
}

// ---------------------------------------------------------------------------
// Probe: edge_index is int64 in the reference, but JAX without x64 silently
// emits int32. Values are in [0, 100000) so if int64, every odd 32-bit word
// of the first 8 entries is zero. False-positive prob for int32 ~ (1e-5)^8.
__global__ void detect_idx_kernel(const unsigned int* __restrict__ w) {
    int is64 = 1;
    for (int i = 0; i < 8; i++)
        if (w[2 * i + 1] != 0u) is64 = 0;
    g_idx_is64 = is64;
}

// ---------------------------------------------------------------------------
// Node kernel: g_src = h@W_src+b, g_dst = h@W_dst+b, out = sigmoid(mlp(g_dst))*g_dst
__global__ __launch_bounds__(128) void node_kernel(
    const float* __restrict__ h,
    const float* __restrict__ W_src, const float* __restrict__ b_src,
    const float* __restrict__ W_dst, const float* __restrict__ b_dst,
    const float* __restrict__ Wa1, const float* __restrict__ ba1,
    const float* __restrict__ Wa2, const float* __restrict__ ba2,
    float* __restrict__ out)
{
    __shared__ float WsT[FF * FF];    // [j][k]
    __shared__ float WdT[FF * FF];
    __shared__ float W1T[HID * FF];   // [j][k]
    __shared__ float W2T[HH * HID];   // [t][j]
    __shared__ float bs[FF], bd[FF], b1[HID], b2[HH];

    int tid = threadIdx.x;
    for (int i = tid; i < FF * FF; i += 128) {
        int k = i >> 6, j = i & 63;
        WsT[j * FF + k] = W_src[i];
        WdT[j * FF + k] = W_dst[i];
    }
    for (int i = tid; i < HID * FF; i += 128) {
        int k = i / HID, j = i % HID;     // Wa1 is [F][HID]
        W1T[j * FF + k] = Wa1[i];
    }
    for (int i = tid; i < HH * HID; i += 128) {
        int k = i / HH, j = i % HH;       // Wa2 is [HID][H]
        W2T[j * HID + k] = Wa2[i];
    }
    if (tid < FF) { bs[tid] = b_src[tid]; bd[tid] = b_dst[tid]; }
    if (tid < HID) b1[tid] = ba1[tid];
    if (tid < HH)  b2[tid] = ba2[tid];
    __syncthreads();

    int node = blockIdx.x * 128 + tid;
    if (node >= NN) return;

    float hr[FF];
    {
        const float4* hp = (const float4*)(h + (size_t)node * FF);
        #pragma unroll
        for (int k4 = 0; k4 < FF / 4; k4++) {
            float4 v = hp[k4];
            hr[4 * k4 + 0] = v.x; hr[4 * k4 + 1] = v.y;
            hr[4 * k4 + 2] = v.z; hr[4 * k4 + 3] = v.w;
        }
    }

    // g_src -> gmem (not kept)
    {
        float4* gp = (float4*)(g_src_buf + (size_t)node * FF);
        #pragma unroll
        for (int j = 0; j < FF; j += 4) {
            float a0 = bs[j], a1 = bs[j + 1], a2 = bs[j + 2], a3 = bs[j + 3];
            #pragma unroll
            for (int k = 0; k < FF; k += 4) {
                float4 w0 = *(const float4*)&WsT[(j + 0) * FF + k];
                float4 w1 = *(const float4*)&WsT[(j + 1) * FF + k];
                float4 w2 = *(const float4*)&WsT[(j + 2) * FF + k];
                float4 w3 = *(const float4*)&WsT[(j + 3) * FF + k];
                a0 += hr[k] * w0.x + hr[k + 1] * w0.y + hr[k + 2] * w0.z + hr[k + 3] * w0.w;
                a1 += hr[k] * w1.x + hr[k + 1] * w1.y + hr[k + 2] * w1.z + hr[k + 3] * w1.w;
                a2 += hr[k] * w2.x + hr[k + 1] * w2.y + hr[k + 2] * w2.z + hr[k + 3] * w2.w;
                a3 += hr[k] * w3.x + hr[k + 1] * w3.y + hr[k + 2] * w3.z + hr[k + 3] * w3.w;
            }
            gp[j >> 2] = make_float4(a0, a1, a2, a3);
        }
    }

    // g_dst -> regs + gmem
    float gd[FF];
    {
        float4* gp = (float4*)(g_dst_buf + (size_t)node * FF);
        #pragma unroll
        for (int j = 0; j < FF; j += 4) {
            float a0 = bd[j], a1 = bd[j + 1], a2 = bd[j + 2], a3 = bd[j + 3];
            #pragma unroll
            for (int k = 0; k < FF; k += 4) {
                float4 w0 = *(const float4*)&WdT[(j + 0) * FF + k];
                float4 w1 = *(const float4*)&WdT[(j + 1) * FF + k];
                float4 w2 = *(const float4*)&WdT[(j + 2) * FF + k];
                float4 w3 = *(const float4*)&WdT[(j + 3) * FF + k];
                a0 += hr[k] * w0.x + hr[k + 1] * w0.y + hr[k + 2] * w0.z + hr[k + 3] * w0.w;
                a1 += hr[k] * w1.x + hr[k + 1] * w1.y + hr[k + 2] * w1.z + hr[k + 3] * w1.w;
                a2 += hr[k] * w2.x + hr[k + 1] * w2.y + hr[k + 2] * w2.z + hr[k + 3] * w2.w;
                a3 += hr[k] * w3.x + hr[k + 1] * w3.y + hr[k + 2] * w3.z + hr[k + 3] * w3.w;
            }
            gd[j + 0] = a0; gd[j + 1] = a1; gd[j + 2] = a2; gd[j + 3] = a3;
            gp[j >> 2] = make_float4(a0, a1, a2, a3);
        }
    }

    // attention MLP on g_dst
    float lm[FF];
    #pragma unroll
    for (int k = 0; k < FF; k++) lm[k] = leaky(gd[k]);

    float y1[HID];
    #pragma unroll
    for (int j = 0; j < HID; j += 4) {
        float a0 = b1[j], a1 = b1[j + 1], a2 = b1[j + 2], a3 = b1[j + 3];
        #pragma unroll
        for (int k = 0; k < FF; k += 4) {
            float4 w0 = *(const float4*)&W1T[(j + 0) * FF + k];
            float4 w1 = *(const float4*)&W1T[(j + 1) * FF + k];
            float4 w2 = *(const float4*)&W1T[(j + 2) * FF + k];
            float4 w3 = *(const float4*)&W1T[(j + 3) * FF + k];
            a0 += lm[k] * w0.x + lm[k + 1] * w0.y + lm[k + 2] * w0.z + lm[k + 3] * w0.w;
            a1 += lm[k] * w1.x + lm[k + 1] * w1.y + lm[k + 2] * w1.z + lm[k + 3] * w1.w;
            a2 += lm[k] * w2.x + lm[k + 1] * w2.y + lm[k + 2] * w2.z + lm[k + 3] * w2.w;
            a3 += lm[k] * w3.x + lm[k + 1] * w3.y + lm[k + 2] * w3.z + lm[k + 3] * w3.w;
        }
        y1[j + 0] = leaky(a0); y1[j + 1] = leaky(a1);
        y1[j + 2] = leaky(a2); y1[j + 3] = leaky(a3);
    }

    float att[HH];
    #pragma unroll
    for (int t = 0; t < HH; t++) {
        float a = b2[t];
        #pragma unroll
        for (int j = 0; j < HID; j += 4) {
            float4 w = *(const float4*)&W2T[t * HID + j];
            a += y1[j] * w.x + y1[j + 1] * w.y + y1[j + 2] * w.z + y1[j + 3] * w.w;
        }
        att[t] = sigm(a);
    }

    // out = a_dst * g_dst  (initializes output; edge kernel atomically adds)
    float4* op = (float4*)(out + (size_t)node * FF);
    #pragma unroll
    for (int t = 0; t < HH; t++) {
        float a = att[t];
        op[2 * t + 0] = make_float4(a * gd[t * 8 + 0], a * gd[t * 8 + 1],
                                    a * gd[t * 8 + 2], a * gd[t * 8 + 3]);
        op[2 * t + 1] = make_float4(a * gd[t * 8 + 4], a * gd[t * 8 + 5],
                                    a * gd[t * 8 + 6], a * gd[t * 8 + 7]);
    }
}

// ---------------------------------------------------------------------------
// Edge kernel: msg = g_src[src]+g_dst[dst]; a = sigmoid(mlp(msg));
// out[dst] += a[h] * g_src[src] (per head)
__global__ __launch_bounds__(128) void edge_kernel(
    const void* __restrict__ edge_index,
    const float* __restrict__ Wa1, const float* __restrict__ ba1,
    const float* __restrict__ Wa2, const float* __restrict__ ba2,
    float* __restrict__ out)
{
    __shared__ float W1T[HID * FF];
    __shared__ float W2T[HH * HID];
    __shared__ float b1[HID], b2[HH];

    int tid = threadIdx.x;
    for (int i = tid; i < HID * FF; i += 128) {
        int k = i / HID, j = i % HID;     // Wa1_src is [F][HID]
        W1T[j * FF + k] = Wa1[i];
    }
    for (int i = tid; i < HH * HID; i += 128) {
        int k = i / HH, j = i % HH;       // Wa2_src is [HID][H]
        W2T[j * HID + k] = Wa2[i];
    }
    if (tid < HID) b1[tid] = ba1[tid];
    if (tid < HH)  b2[tid] = ba2[tid];
    __syncthreads();

    int e = blockIdx.x * 128 + tid;
    if (e >= EE) return;

    long long src, dst;
    if (g_idx_is64) {
        const long long* ei = (const long long*)edge_index;
        src = ei[e]; dst = ei[EE + e];
    } else {
        const int* ei = (const int*)edge_index;
        src = ei[e]; dst = ei[EE + e];
    }

    float ms[FF];   // msg_src = g_src[src] (kept for aggregation product)
    float lm[FF];   // leaky(msg)
    {
        const float4* sp = (const float4*)(g_src_buf + src * FF);
        const float4* dp = (const float4*)(g_dst_buf + dst * FF);
        #pragma unroll
        for (int k4 = 0; k4 < FF / 4; k4++) {
            float4 a = sp[k4];
            float4 b = dp[k4];
            ms[4 * k4 + 0] = a.x; ms[4 * k4 + 1] = a.y;
            ms[4 * k4 + 2] = a.z; ms[4 * k4 + 3] = a.w;
            lm[4 * k4 + 0] = leaky(a.x + b.x);
            lm[4 * k4 + 1] = leaky(a.y + b.y);
            lm[4 * k4 + 2] = leaky(a.z + b.z);
            lm[4 * k4 + 3] = leaky(a.w + b.w);
        }
    }

    float y1[HID];
    #pragma unroll
    for (int j = 0; j < HID; j += 4) {
        float a0 = b1[j], a1 = b1[j + 1], a2 = b1[j + 2], a3 = b1[j + 3];
        #pragma unroll
        for (int k = 0; k < FF; k += 4) {
            float4 w0 = *(const float4*)&W1T[(j + 0) * FF + k];
            float4 w1 = *(const float4*)&W1T[(j + 1) * FF + k];
            float4 w2 = *(const float4*)&W1T[(j + 2) * FF + k];
            float4 w3 = *(const float4*)&W1T[(j + 3) * FF + k];
            a0 += lm[k] * w0.x + lm[k + 1] * w0.y + lm[k + 2] * w0.z + lm[k + 3] * w0.w;
            a1 += lm[k] * w1.x + lm[k + 1] * w1.y + lm[k + 2] * w1.z + lm[k + 3] * w1.w;
            a2 += lm[k] * w2.x + lm[k + 1] * w2.y + lm[k + 2] * w2.z + lm[k + 3] * w2.w;
            a3 += lm[k] * w3.x + lm[k + 1] * w3.y + lm[k + 2] * w3.z + lm[k + 3] * w3.w;
        }
        y1[j + 0] = leaky(a0); y1[j + 1] = leaky(a1);
        y1[j + 2] = leaky(a2); y1[j + 3] = leaky(a3);
    }

    float att[HH];
    #pragma unroll
    for (int t = 0; t < HH; t++) {
        float a = b2[t];
        #pragma unroll
        for (int j = 0; j < HID; j += 4) {
            float4 w = *(const float4*)&W2T[t * HID + j];
            a += y1[j] * w.x + y1[j + 1] * w.y + y1[j + 2] * w.z + y1[j + 3] * w.w;
        }
        att[t] = sigm(a);
    }

    float* op = out + dst * FF;
    #pragma unroll
    for (int t = 0; t < HH; t++) {
        float a = att[t];
        red4(op + t * 8,     a * ms[t * 8 + 0], a * ms[t * 8 + 1],
                             a * ms[t * 8 + 2], a * ms[t * 8 + 3]);
        red4(op + t * 8 + 4, a * ms[t * 8 + 4], a * ms[t * 8 + 5],
                             a * ms[t * 8 + 6], a * ms[t * 8 + 7]);
    }
}

// ---------------------------------------------------------------------------
extern "C" void kernel_launch(void* const* d_in, const int* in_sizes, int n_in,
                              void* d_out, int out_size)
{
    const float* h      = (const float*)d_in[0];
    const float* W_src  = (const float*)d_in[1];
    const float* b_src  = (const float*)d_in[2];
    const float* W_dst  = (const float*)d_in[3];
    const float* b_dst  = (const float*)d_in[4];
    const float* Wa1_s  = (const float*)d_in[5];
    const float* ba1_s  = (const float*)d_in[6];
    const float* Wa2_s  = (const float*)d_in[7];
    const float* ba2_s  = (const float*)d_in[8];
    const float* Wa1_d  = (const float*)d_in[9];
    const float* ba1_d  = (const float*)d_in[10];
    const float* Wa2_d  = (const float*)d_in[11];
    const float* ba2_d  = (const float*)d_in[12];
    const void*  eidx   = (const void*)d_in[13];
    float* out = (float*)d_out;

    detect_idx_kernel<<<1, 1>>>((const unsigned int*)eidx);

    node_kernel<<<(NN + 127) / 128, 128>>>(
        h, W_src, b_src, W_dst, b_dst,
        Wa1_d, ba1_d, Wa2_d, ba2_d, out);

    edge_kernel<<<(EE + 127) / 128, 128>>>(
        eidx, Wa1_s, ba1_s, Wa2_s, ba2_s, out);
}